// round 14
// baseline (speedup 1.0000x reference)
#include <cuda_runtime.h>
#include <cuda_fp16.h>
#include <cstdint>

// ---------------------------------------------------------------------------
// TinyFormerEncoder R13:
//  - K staging ELIMINATED: S=QK^T B-fragments are the K-gemm C-fragments
//    repacked in-register (same thread owns both) — no smem round trip.
//  - 1-term attention: Q and P hi-only fp16 (error budget: ~2e-4 predicted,
//    5x under tolerance). S gemm = 4 mma/batch with zero LDS.
//  - Everything else from R12: conflict-free strides, hi-only weights,
//    batch pairing, FFN halves, 4 blocks/SM (16 warps, RF ceiling).
// ---------------------------------------------------------------------------

namespace {
constexpr int THREADS = 128;          // 4 warps
constexpr int NB = 8;                 // batches per warp (4 pairs)
constexpr int BATCHES_PER_BLOCK = 4 * NB;  // 32

// ushort (fp16) offsets in dynamic smem — hi weight planes, stride 40
constexpr int WQH = 0;                     // 32 x 40
constexpr int WKH = 1280;
constexpr int WVH = 2560;
constexpr int WOH = 3840;
constexpr int W1H = 5120;                  // 64 x 40
constexpr int W2H = 7680;                  // 32 x 72
constexpr int BIASU  = 9984;               // 224 floats = 448 ushorts
constexpr int STAGEU = 10432;              // per-warp staging base
constexpr int VS = 24;                     // vT row stride — conflict-free
constexpr int BATCH_STAGE = 32 * VS;       // 768 (vT hi plane only)
constexpr int WARP_STAGE  = 2 * BATCH_STAGE;
constexpr int SMEM_BYTES = (STAGEU + 4 * WARP_STAGE) * 2;  // 33152
constexpr float SCALE = 0.17677669529663687f;  // 1/sqrt(32)
}

__device__ __forceinline__ uint32_t packh(float e0, float e1) {
    __half2 h = __float22half2_rn(make_float2(e0, e1));   // e0 -> low half
    return *(uint32_t*)&h;
}
__device__ __forceinline__ unsigned short f2h(float v) {
    __half h = __float2half_rn(v);
    return *(unsigned short*)&h;
}

__device__ __forceinline__ void mma16816(float &c0, float &c1, float &c2, float &c3,
                                         uint32_t a0, uint32_t a1, uint32_t a2, uint32_t a3,
                                         uint32_t b0, uint32_t b1) {
    asm("mma.sync.aligned.m16n8k16.row.col.f32.f16.f16.f32 "
        "{%0,%1,%2,%3}, {%4,%5,%6,%7}, {%8,%9}, {%0,%1,%2,%3};"
        : "+f"(c0), "+f"(c1), "+f"(c2), "+f"(c3)
        : "r"(a0), "r"(a1), "r"(a2), "r"(a3), "r"(b0), "r"(b1));
}

// hi-only C->A conversion
template <int KCH>
__device__ __forceinline__ void c2a_hi(const float *C, uint32_t *ah) {
#pragma unroll
    for (int kc = 0; kc < KCH; kc++) {
        ah[kc*4+0] = packh(C[8*kc+0], C[8*kc+1]);
        ah[kc*4+1] = packh(C[8*kc+2], C[8*kc+3]);
        ah[kc*4+2] = packh(C[8*kc+4], C[8*kc+5]);
        ah[kc*4+3] = packh(C[8*kc+6], C[8*kc+7]);
    }
}

// 1-term batch-paired weight gemm (A-hi x B-hi)
template <int KCH, int NCH, int RS>
__device__ __forceinline__ void gemm1w(float *CA, float *CB,
                                       const uint32_t *ahA, const uint32_t *ahB,
                                       const unsigned short *wh, int g, int t) {
#pragma unroll
    for (int j = 0; j < NCH; j++) {
#pragma unroll
        for (int kc = 0; kc < KCH; kc++) {
            const unsigned short *ph = wh + (8*j + g)*RS + kc*16 + 2*t;
            uint32_t b0 = *(const uint32_t*)ph, b1 = *(const uint32_t*)(ph + 8);
            mma16816(CA[j*4+0],CA[j*4+1],CA[j*4+2],CA[j*4+3],
                     ahA[kc*4+0],ahA[kc*4+1],ahA[kc*4+2],ahA[kc*4+3], b0,b1);
            mma16816(CB[j*4+0],CB[j*4+1],CB[j*4+2],CB[j*4+3],
                     ahB[kc*4+0],ahB[kc*4+1],ahB[kc*4+2],ahB[kc*4+3], b0,b1);
        }
    }
}

__global__ void __launch_bounds__(THREADS, 4)
tinyformer_tc_kernel(const float *__restrict__ x,
                     const float *__restrict__ Wq, const float *__restrict__ bq,
                     const float *__restrict__ Wk, const float *__restrict__ bk,
                     const float *__restrict__ Wv, const float *__restrict__ bv,
                     const float *__restrict__ Wo, const float *__restrict__ bo,
                     const float *__restrict__ W1, const float *__restrict__ b1,
                     const float *__restrict__ W2, const float *__restrict__ b2,
                     float *__restrict__ out, int B)
{
    extern __shared__ unsigned short sm16[];
    float *smf = (float*)(sm16 + BIASU);
    const int tid = threadIdx.x;

    // ---- stage weights: transpose to fp16 hi planes (stride 40 / 72) ----
    for (int i = tid; i < 1024; i += THREADS) {
        int d = i >> 5, j = i & 31;
        int o = j*40 + d;
        sm16[WQH + o] = f2h(Wq[i]);
        sm16[WKH + o] = f2h(Wk[i]);
        sm16[WVH + o] = f2h(Wv[i]);
        sm16[WOH + o] = f2h(Wo[i]);
    }
    for (int i = tid; i < 2048; i += THREADS) {
        {   int d = i >> 6, j = i & 63;
            sm16[W1H + j*40 + d] = f2h(W1[i]); }
        {   int h = i >> 5, j = i & 31;
            sm16[W2H + j*72 + h] = f2h(W2[i]); }
    }
    if (tid < 32) {
        smf[0   + tid] = bq[tid]; smf[32 + tid] = bk[tid]; smf[64 + tid] = bv[tid];
        smf[96  + tid] = bo[tid]; smf[192 + tid] = b2[tid];
    }
    if (tid < 64) smf[128 + tid] = b1[tid];
    __syncthreads();

    const int warp = tid >> 5, lane = tid & 31;
    const int g = lane >> 2, t = lane & 3;
    unsigned short *vtA = sm16 + STAGEU + warp * WARP_STAGE;
    unsigned short *vtB = vtA + BATCH_STAGE;

    for (int it = 0; it < NB/2; it++) {
        size_t b0 = (size_t)blockIdx.x * BATCHES_PER_BLOCK + warp * NB + 2*it;
        if (b0 >= (size_t)B) continue;           // warp-uniform
        size_t b1s = b0 + 1;
        const bool v1 = b1s < (size_t)B;
        if (!v1) b1s = b0;

        // ---- x (both batches) in C-fragment layout, fp32 ----
        const float2 *xpA = (const float2*)(x + b0 * 512);
        const float2 *xpB = (const float2*)(x + b1s * 512);
        float xcA[16], xcB[16];
#pragma unroll
        for (int nc = 0; nc < 4; nc++) {
            float2 p0 = xpA[g*16 + nc*4 + t], p1 = xpA[(g+8)*16 + nc*4 + t];
            xcA[nc*4+0] = p0.x; xcA[nc*4+1] = p0.y;
            xcA[nc*4+2] = p1.x; xcA[nc*4+3] = p1.y;
            float2 q0 = xpB[g*16 + nc*4 + t], q1 = xpB[(g+8)*16 + nc*4 + t];
            xcB[nc*4+0] = q0.x; xcB[nc*4+1] = q0.y;
            xcB[nc*4+2] = q1.x; xcB[nc*4+3] = q1.y;
        }
        uint32_t xahA[8], xahB[8];
        c2a_hi<2>(xcA, xahA);
        c2a_hi<2>(xcB, xahB);

        float CA[16], CB[16];

        // ---- K (both): C-fragments repacked DIRECTLY into S B-fragments ----
#pragma unroll
        for (int i2 = 0; i2 < 16; i2++) { CA[i2] = 0.f; CB[i2] = 0.f; }
        gemm1w<2,4,40>(CA, CB, xahA, xahB, sm16 + WKH, g, t);
        uint32_t kbA[8], kbB[8];
#pragma unroll
        for (int kc = 0; kc < 2; kc++) {
            float2 bb0 = *(const float2*)(smf + 32 + 16*kc + 2*t);      // cols 16kc+2t
            float2 bb1 = *(const float2*)(smf + 32 + 16*kc + 8 + 2*t);  // cols 16kc+8+2t
#pragma unroll
            for (int j = 0; j < 2; j++) {
                // b0: K[row 8j+g][k=16kc+2t,+1] = C[8kc+2j], C[8kc+2j+1]
                kbA[kc*4 + j*2 + 0] = packh(CA[8*kc + 2*j]     + bb0.x, CA[8*kc + 2*j + 1]     + bb0.y);
                kbA[kc*4 + j*2 + 1] = packh(CA[8*kc + 4 + 2*j] + bb1.x, CA[8*kc + 4 + 2*j + 1] + bb1.y);
                kbB[kc*4 + j*2 + 0] = packh(CB[8*kc + 2*j]     + bb0.x, CB[8*kc + 2*j + 1]     + bb0.y);
                kbB[kc*4 + j*2 + 1] = packh(CB[8*kc + 4 + 2*j] + bb1.x, CB[8*kc + 4 + 2*j + 1] + bb1.y);
            }
        }

        // ---- V (both) -> hi-only TRANSPOSED staging ----
#pragma unroll
        for (int i2 = 0; i2 < 16; i2++) { CA[i2] = 0.f; CB[i2] = 0.f; }
        gemm1w<2,4,40>(CA, CB, xahA, xahB, sm16 + WVH, g, t);
#pragma unroll
        for (int nc = 0; nc < 4; nc++) {
            float2 bb = *(const float2*)(smf + 64 + 8*nc + 2*t);
            int col0 = 8*nc + 2*t;
#pragma unroll
            for (int m = 0; m < 4; m++) {
                int col = col0 + (m & 1);
                int row = (m < 2) ? g : g + 8;
                vtA[col*VS + row] = f2h(CA[nc*4+m] + ((m & 1) ? bb.y : bb.x));
                vtB[col*VS + row] = f2h(CB[nc*4+m] + ((m & 1) ? bb.y : bb.x));
            }
        }

        // ---- Q (both) -> scaled hi-only A-fragments ----
#pragma unroll
        for (int i2 = 0; i2 < 16; i2++) { CA[i2] = 0.f; CB[i2] = 0.f; }
        gemm1w<2,4,40>(CA, CB, xahA, xahB, sm16 + WQH, g, t);
        uint32_t qahA[8], qahB[8];
#pragma unroll
        for (int nc = 0; nc < 4; nc++) {
            float2 bb = *(const float2*)(smf + 0 + 8*nc + 2*t);
            CA[nc*4+0] = (CA[nc*4+0] + bb.x) * SCALE;
            CA[nc*4+1] = (CA[nc*4+1] + bb.y) * SCALE;
            CA[nc*4+2] = (CA[nc*4+2] + bb.x) * SCALE;
            CA[nc*4+3] = (CA[nc*4+3] + bb.y) * SCALE;
            CB[nc*4+0] = (CB[nc*4+0] + bb.x) * SCALE;
            CB[nc*4+1] = (CB[nc*4+1] + bb.y) * SCALE;
            CB[nc*4+2] = (CB[nc*4+2] + bb.x) * SCALE;
            CB[nc*4+3] = (CB[nc*4+3] + bb.y) * SCALE;
        }
        c2a_hi<2>(CA, qahA);
        c2a_hi<2>(CB, qahB);
        __syncwarp();   // vT staging visible within warp

        // ---- S = Q@K^T (1-term, register B), softmax, P frags (per batch) ----
        uint32_t pahA[4], pahB[4];
#pragma unroll
        for (int side = 0; side < 2; side++) {
            const uint32_t *kb = side ? kbB : kbA;
            const uint32_t *qa = side ? qahB : qahA;
            float s[8];
#pragma unroll
            for (int i2 = 0; i2 < 8; i2++) s[i2] = 0.f;
#pragma unroll
            for (int j = 0; j < 2; j++)
#pragma unroll
                for (int kc = 0; kc < 2; kc++)
                    mma16816(s[j*4+0],s[j*4+1],s[j*4+2],s[j*4+3],
                             qa[kc*4+0],qa[kc*4+1],qa[kc*4+2],qa[kc*4+3],
                             kb[kc*4+j*2+0], kb[kc*4+j*2+1]);

            float m0 = fmaxf(fmaxf(s[0], s[1]), fmaxf(s[4], s[5]));
            float m1 = fmaxf(fmaxf(s[2], s[3]), fmaxf(s[6], s[7]));
            m0 = fmaxf(m0, __shfl_xor_sync(0xffffffffu, m0, 1));
            m0 = fmaxf(m0, __shfl_xor_sync(0xffffffffu, m0, 2));
            m1 = fmaxf(m1, __shfl_xor_sync(0xffffffffu, m1, 1));
            m1 = fmaxf(m1, __shfl_xor_sync(0xffffffffu, m1, 2));
            s[0] = __expf(s[0] - m0); s[1] = __expf(s[1] - m0);
            s[4] = __expf(s[4] - m0); s[5] = __expf(s[5] - m0);
            s[2] = __expf(s[2] - m1); s[3] = __expf(s[3] - m1);
            s[6] = __expf(s[6] - m1); s[7] = __expf(s[7] - m1);
            float t0 = s[0] + s[1] + s[4] + s[5];
            float t1 = s[2] + s[3] + s[6] + s[7];
            t0 += __shfl_xor_sync(0xffffffffu, t0, 1);
            t0 += __shfl_xor_sync(0xffffffffu, t0, 2);
            t1 += __shfl_xor_sync(0xffffffffu, t1, 1);
            t1 += __shfl_xor_sync(0xffffffffu, t1, 2);
            float i0 = 1.f / t0, i1 = 1.f / t1;
            s[0] *= i0; s[1] *= i0; s[4] *= i0; s[5] *= i0;
            s[2] *= i1; s[3] *= i1; s[6] *= i1; s[7] *= i1;

            uint32_t *ph = side ? pahB : pahA;
            ph[0] = packh(s[0], s[1]);
            ph[1] = packh(s[2], s[3]);
            ph[2] = packh(s[4], s[5]);
            ph[3] = packh(s[6], s[7]);
        }

        // ---- ctx = P@V (1-term, per batch; B from vT smem) ----
#pragma unroll
        for (int i2 = 0; i2 < 16; i2++) { CA[i2] = 0.f; CB[i2] = 0.f; }
#pragma unroll
        for (int j = 0; j < 4; j++) {
            const unsigned short *pA = vtA + (8*j + g)*VS + 2*t;
            uint32_t a0 = *(const uint32_t*)pA, a1 = *(const uint32_t*)(pA + 8);
            mma16816(CA[j*4+0],CA[j*4+1],CA[j*4+2],CA[j*4+3],
                     pahA[0],pahA[1],pahA[2],pahA[3], a0,a1);
            const unsigned short *pB = vtB + (8*j + g)*VS + 2*t;
            uint32_t c0 = *(const uint32_t*)pB, c1 = *(const uint32_t*)(pB + 8);
            mma16816(CB[j*4+0],CB[j*4+1],CB[j*4+2],CB[j*4+3],
                     pahB[0],pahB[1],pahB[2],pahB[3], c0,c1);
        }

        // ---- y = x + ctx@Wo + bo ----
        uint32_t cahA[8], cahB[8];
        c2a_hi<2>(CA, cahA);
        c2a_hi<2>(CB, cahB);
        float yvA[16], yvB[16];
#pragma unroll
        for (int i2 = 0; i2 < 16; i2++) { yvA[i2] = 0.f; yvB[i2] = 0.f; }
        gemm1w<2,4,40>(yvA, yvB, cahA, cahB, sm16 + WOH, g, t);
#pragma unroll
        for (int nc = 0; nc < 4; nc++) {
            float2 bb = *(const float2*)(smf + 96 + 8*nc + 2*t);
            yvA[nc*4+0] += xcA[nc*4+0] + bb.x;
            yvA[nc*4+1] += xcA[nc*4+1] + bb.y;
            yvA[nc*4+2] += xcA[nc*4+2] + bb.x;
            yvA[nc*4+3] += xcA[nc*4+3] + bb.y;
            yvB[nc*4+0] += xcB[nc*4+0] + bb.x;
            yvB[nc*4+1] += xcB[nc*4+1] + bb.y;
            yvB[nc*4+2] += xcB[nc*4+2] + bb.x;
            yvB[nc*4+3] += xcB[nc*4+3] + bb.y;
        }

        // ---- FFN in two halves ----
        uint32_t yahA[8], yahB[8];
        c2a_hi<2>(yvA, yahA);
        c2a_hi<2>(yvB, yahB);
        float zvA[16], zvB[16];
#pragma unroll
        for (int i2 = 0; i2 < 16; i2++) { zvA[i2] = 0.f; zvB[i2] = 0.f; }
#pragma unroll
        for (int fh = 0; fh < 2; fh++) {
            float hbA[16], hbB[16];
#pragma unroll
            for (int i2 = 0; i2 < 16; i2++) { hbA[i2] = 0.f; hbB[i2] = 0.f; }
            gemm1w<2,4,40>(hbA, hbB, yahA, yahB, sm16 + W1H + fh*32*40, g, t);
#pragma unroll
            for (int nc = 0; nc < 4; nc++) {
                float2 bb = *(const float2*)(smf + 128 + fh*32 + 8*nc + 2*t);
                hbA[nc*4+0] = fmaxf(hbA[nc*4+0] + bb.x, 0.f);
                hbA[nc*4+1] = fmaxf(hbA[nc*4+1] + bb.y, 0.f);
                hbA[nc*4+2] = fmaxf(hbA[nc*4+2] + bb.x, 0.f);
                hbA[nc*4+3] = fmaxf(hbA[nc*4+3] + bb.y, 0.f);
                hbB[nc*4+0] = fmaxf(hbB[nc*4+0] + bb.x, 0.f);
                hbB[nc*4+1] = fmaxf(hbB[nc*4+1] + bb.y, 0.f);
                hbB[nc*4+2] = fmaxf(hbB[nc*4+2] + bb.x, 0.f);
                hbB[nc*4+3] = fmaxf(hbB[nc*4+3] + bb.y, 0.f);
            }
            uint32_t hahA[8], hahB[8];
            c2a_hi<2>(hbA, hahA);
            c2a_hi<2>(hbB, hahB);
            gemm1w<2,4,72>(zvA, zvB, hahA, hahB, sm16 + W2H + fh*32, g, t);
        }

        // ---- z = y + (accumulated) + b2; store ----
        float2 *opA = (float2*)(out + b0 * 512);
#pragma unroll
        for (int nc = 0; nc < 4; nc++) {
            float2 bb = *(const float2*)(smf + 192 + 8*nc + 2*t);
            opA[g*16 + nc*4 + t]     = make_float2(zvA[nc*4+0] + yvA[nc*4+0] + bb.x,
                                                   zvA[nc*4+1] + yvA[nc*4+1] + bb.y);
            opA[(g+8)*16 + nc*4 + t] = make_float2(zvA[nc*4+2] + yvA[nc*4+2] + bb.x,
                                                   zvA[nc*4+3] + yvA[nc*4+3] + bb.y);
        }
        if (v1) {
            float2 *opB = (float2*)(out + b1s * 512);
#pragma unroll
            for (int nc = 0; nc < 4; nc++) {
                float2 bb = *(const float2*)(smf + 192 + 8*nc + 2*t);
                opB[g*16 + nc*4 + t]     = make_float2(zvB[nc*4+0] + yvB[nc*4+0] + bb.x,
                                                       zvB[nc*4+1] + yvB[nc*4+1] + bb.y);
                opB[(g+8)*16 + nc*4 + t] = make_float2(zvB[nc*4+2] + yvB[nc*4+2] + bb.x,
                                                       zvB[nc*4+3] + yvB[nc*4+3] + bb.y);
            }
        }
        __syncwarp();   // vT staging reuse barrier for next pair
    }
}

extern "C" void kernel_launch(void* const* d_in, const int* in_sizes, int n_in,
                              void* d_out, int out_size)
{
    const float* x  = (const float*)d_in[0];
    const float* Wq = (const float*)d_in[1];
    const float* bq = (const float*)d_in[2];
    const float* Wk = (const float*)d_in[3];
    const float* bk = (const float*)d_in[4];
    const float* Wv = (const float*)d_in[5];
    const float* bv = (const float*)d_in[6];
    const float* Wo = (const float*)d_in[7];
    const float* bo = (const float*)d_in[8];
    const float* W1 = (const float*)d_in[9];
    const float* b1 = (const float*)d_in[10];
    const float* W2 = (const float*)d_in[11];
    const float* b2 = (const float*)d_in[12];
    float* out = (float*)d_out;

    const int B = in_sizes[0] / 512;                                    // 65536
    const int blocks = (B + BATCHES_PER_BLOCK - 1) / BATCHES_PER_BLOCK; // 2048

    cudaFuncSetAttribute(tinyformer_tc_kernel,
                         cudaFuncAttributeMaxDynamicSharedMemorySize, SMEM_BYTES);
    tinyformer_tc_kernel<<<blocks, THREADS, SMEM_BYTES>>>(x, Wq, bq, Wk, bk, Wv, bv,
                                                          Wo, bo, W1, b1, W2, b2, out, B);
}

// round 15
// speedup vs baseline: 1.0429x; 1.0429x over previous
#include <cuda_runtime.h>
#include <cuda_fp16.h>
#include <cstdint>

// ---------------------------------------------------------------------------
// TinyFormerEncoder R14: epilogue folding.
//  - C-fragments initialized to BIAS instead of zero (mma accumulates onto it)
//  - 1/sqrt(D) folded into staged Wq/bq (Q comes out pre-scaled)
//  - y initialized to x + bo, z initialized to y + b2 (stores are plain)
//  Removes ~300 scalar instructions per batch-pair from the issue stream.
//  Structure from R13: K S-fragments built in-register (no K smem), 1-term
//  fp16 everywhere, batch pairing, conflict-free strides, 4 blocks/SM.
// ---------------------------------------------------------------------------

namespace {
constexpr int THREADS = 128;          // 4 warps
constexpr int NB = 8;                 // batches per warp (4 pairs)
constexpr int BATCHES_PER_BLOCK = 4 * NB;  // 32

// ushort (fp16) offsets in dynamic smem — hi weight planes, stride 40
constexpr int WQH = 0;                     // 32 x 40 (pre-scaled by 1/sqrt(D))
constexpr int WKH = 1280;
constexpr int WVH = 2560;
constexpr int WOH = 3840;
constexpr int W1H = 5120;                  // 64 x 40
constexpr int W2H = 7680;                  // 32 x 72
constexpr int BIASU  = 9984;               // 224 floats = 448 ushorts
constexpr int STAGEU = 10432;              // per-warp staging base
constexpr int VS = 24;                     // vT row stride — conflict-free
constexpr int BATCH_STAGE = 32 * VS;       // 768 (vT hi plane only)
constexpr int WARP_STAGE  = 2 * BATCH_STAGE;
constexpr int SMEM_BYTES = (STAGEU + 4 * WARP_STAGE) * 2;  // 33152
constexpr float SCALE = 0.17677669529663687f;  // 1/sqrt(32)
}

__device__ __forceinline__ uint32_t packh(float e0, float e1) {
    __half2 h = __float22half2_rn(make_float2(e0, e1));   // e0 -> low half
    return *(uint32_t*)&h;
}
__device__ __forceinline__ unsigned short f2h(float v) {
    __half h = __float2half_rn(v);
    return *(unsigned short*)&h;
}

__device__ __forceinline__ void mma16816(float &c0, float &c1, float &c2, float &c3,
                                         uint32_t a0, uint32_t a1, uint32_t a2, uint32_t a3,
                                         uint32_t b0, uint32_t b1) {
    asm("mma.sync.aligned.m16n8k16.row.col.f32.f16.f16.f32 "
        "{%0,%1,%2,%3}, {%4,%5,%6,%7}, {%8,%9}, {%0,%1,%2,%3};"
        : "+f"(c0), "+f"(c1), "+f"(c2), "+f"(c3)
        : "r"(a0), "r"(a1), "r"(a2), "r"(a3), "r"(b0), "r"(b1));
}

// hi-only C->A conversion
template <int KCH>
__device__ __forceinline__ void c2a_hi(const float *C, uint32_t *ah) {
#pragma unroll
    for (int kc = 0; kc < KCH; kc++) {
        ah[kc*4+0] = packh(C[8*kc+0], C[8*kc+1]);
        ah[kc*4+1] = packh(C[8*kc+2], C[8*kc+3]);
        ah[kc*4+2] = packh(C[8*kc+4], C[8*kc+5]);
        ah[kc*4+3] = packh(C[8*kc+6], C[8*kc+7]);
    }
}

// init C-fragment (16 els, 4 n-chunks) with per-column bias
__device__ __forceinline__ void initCb(float *C, const float *bias, int t) {
#pragma unroll
    for (int nc = 0; nc < 4; nc++) {
        float2 bb = *(const float2*)(bias + 8*nc + 2*t);
        C[nc*4+0] = bb.x; C[nc*4+1] = bb.y;
        C[nc*4+2] = bb.x; C[nc*4+3] = bb.y;
    }
}

// 1-term batch-paired weight gemm (A-hi x B-hi)
template <int KCH, int NCH, int RS>
__device__ __forceinline__ void gemm1w(float *CA, float *CB,
                                       const uint32_t *ahA, const uint32_t *ahB,
                                       const unsigned short *wh, int g, int t) {
#pragma unroll
    for (int j = 0; j < NCH; j++) {
#pragma unroll
        for (int kc = 0; kc < KCH; kc++) {
            const unsigned short *ph = wh + (8*j + g)*RS + kc*16 + 2*t;
            uint32_t b0 = *(const uint32_t*)ph, b1 = *(const uint32_t*)(ph + 8);
            mma16816(CA[j*4+0],CA[j*4+1],CA[j*4+2],CA[j*4+3],
                     ahA[kc*4+0],ahA[kc*4+1],ahA[kc*4+2],ahA[kc*4+3], b0,b1);
            mma16816(CB[j*4+0],CB[j*4+1],CB[j*4+2],CB[j*4+3],
                     ahB[kc*4+0],ahB[kc*4+1],ahB[kc*4+2],ahB[kc*4+3], b0,b1);
        }
    }
}

__global__ void __launch_bounds__(THREADS, 4)
tinyformer_tc_kernel(const float *__restrict__ x,
                     const float *__restrict__ Wq, const float *__restrict__ bq,
                     const float *__restrict__ Wk, const float *__restrict__ bk,
                     const float *__restrict__ Wv, const float *__restrict__ bv,
                     const float *__restrict__ Wo, const float *__restrict__ bo,
                     const float *__restrict__ W1, const float *__restrict__ b1,
                     const float *__restrict__ W2, const float *__restrict__ b2,
                     float *__restrict__ out, int B)
{
    extern __shared__ unsigned short sm16[];
    float *smf = (float*)(sm16 + BIASU);
    const int tid = threadIdx.x;

    // ---- stage weights: transpose to fp16 hi planes (Wq pre-scaled) ----
    for (int i = tid; i < 1024; i += THREADS) {
        int d = i >> 5, j = i & 31;
        int o = j*40 + d;
        sm16[WQH + o] = f2h(Wq[i] * SCALE);
        sm16[WKH + o] = f2h(Wk[i]);
        sm16[WVH + o] = f2h(Wv[i]);
        sm16[WOH + o] = f2h(Wo[i]);
    }
    for (int i = tid; i < 2048; i += THREADS) {
        {   int d = i >> 6, j = i & 63;
            sm16[W1H + j*40 + d] = f2h(W1[i]); }
        {   int h = i >> 5, j = i & 31;
            sm16[W2H + j*72 + h] = f2h(W2[i]); }
    }
    if (tid < 32) {
        smf[0   + tid] = bq[tid] * SCALE;   // pre-scaled bq
        smf[32 + tid] = bk[tid]; smf[64 + tid] = bv[tid];
        smf[96  + tid] = bo[tid]; smf[192 + tid] = b2[tid];
    }
    if (tid < 64) smf[128 + tid] = b1[tid];
    __syncthreads();

    const int warp = tid >> 5, lane = tid & 31;
    const int g = lane >> 2, t = lane & 3;
    unsigned short *vtA = sm16 + STAGEU + warp * WARP_STAGE;
    unsigned short *vtB = vtA + BATCH_STAGE;

    for (int it = 0; it < NB/2; it++) {
        size_t b0 = (size_t)blockIdx.x * BATCHES_PER_BLOCK + warp * NB + 2*it;
        if (b0 >= (size_t)B) continue;           // warp-uniform
        size_t b1s = b0 + 1;
        const bool v1 = b1s < (size_t)B;
        if (!v1) b1s = b0;

        // ---- x (both batches) in C-fragment layout, fp32 ----
        const float2 *xpA = (const float2*)(x + b0 * 512);
        const float2 *xpB = (const float2*)(x + b1s * 512);
        float xcA[16], xcB[16];
#pragma unroll
        for (int nc = 0; nc < 4; nc++) {
            float2 p0 = xpA[g*16 + nc*4 + t], p1 = xpA[(g+8)*16 + nc*4 + t];
            xcA[nc*4+0] = p0.x; xcA[nc*4+1] = p0.y;
            xcA[nc*4+2] = p1.x; xcA[nc*4+3] = p1.y;
            float2 q0 = xpB[g*16 + nc*4 + t], q1 = xpB[(g+8)*16 + nc*4 + t];
            xcB[nc*4+0] = q0.x; xcB[nc*4+1] = q0.y;
            xcB[nc*4+2] = q1.x; xcB[nc*4+3] = q1.y;
        }
        uint32_t xahA[8], xahB[8];
        c2a_hi<2>(xcA, xahA);
        c2a_hi<2>(xcB, xahB);

        float CA[16], CB[16];

        // ---- K (both): C init = bk, repack directly into S B-fragments ----
        initCb(CA, smf + 32, t);
        initCb(CB, smf + 32, t);
        gemm1w<2,4,40>(CA, CB, xahA, xahB, sm16 + WKH, g, t);
        uint32_t kbA[8], kbB[8];
#pragma unroll
        for (int kc = 0; kc < 2; kc++) {
#pragma unroll
            for (int j = 0; j < 2; j++) {
                kbA[kc*4 + j*2 + 0] = packh(CA[8*kc + 2*j],     CA[8*kc + 2*j + 1]);
                kbA[kc*4 + j*2 + 1] = packh(CA[8*kc + 4 + 2*j], CA[8*kc + 4 + 2*j + 1]);
                kbB[kc*4 + j*2 + 0] = packh(CB[8*kc + 2*j],     CB[8*kc + 2*j + 1]);
                kbB[kc*4 + j*2 + 1] = packh(CB[8*kc + 4 + 2*j], CB[8*kc + 4 + 2*j + 1]);
            }
        }

        // ---- V (both): C init = bv, hi-only TRANSPOSED staging ----
        initCb(CA, smf + 64, t);
        initCb(CB, smf + 64, t);
        gemm1w<2,4,40>(CA, CB, xahA, xahB, sm16 + WVH, g, t);
#pragma unroll
        for (int nc = 0; nc < 4; nc++) {
            int col0 = 8*nc + 2*t;
#pragma unroll
            for (int m = 0; m < 4; m++) {
                int col = col0 + (m & 1);
                int row = (m < 2) ? g : g + 8;
                vtA[col*VS + row] = f2h(CA[nc*4+m]);
                vtB[col*VS + row] = f2h(CB[nc*4+m]);
            }
        }

        // ---- Q (both): C init = scaled bq; weights pre-scaled ----
        initCb(CA, smf + 0, t);
        initCb(CB, smf + 0, t);
        gemm1w<2,4,40>(CA, CB, xahA, xahB, sm16 + WQH, g, t);
        uint32_t qahA[8], qahB[8];
        c2a_hi<2>(CA, qahA);
        c2a_hi<2>(CB, qahB);
        __syncwarp();   // vT staging visible within warp

        // ---- S = Q@K^T (register B), softmax, P frags (per batch) ----
        uint32_t pahA[4], pahB[4];
#pragma unroll
        for (int side = 0; side < 2; side++) {
            const uint32_t *kb = side ? kbB : kbA;
            const uint32_t *qa = side ? qahB : qahA;
            float s[8];
#pragma unroll
            for (int i2 = 0; i2 < 8; i2++) s[i2] = 0.f;
#pragma unroll
            for (int j = 0; j < 2; j++)
#pragma unroll
                for (int kc = 0; kc < 2; kc++)
                    mma16816(s[j*4+0],s[j*4+1],s[j*4+2],s[j*4+3],
                             qa[kc*4+0],qa[kc*4+1],qa[kc*4+2],qa[kc*4+3],
                             kb[kc*4+j*2+0], kb[kc*4+j*2+1]);

            float m0 = fmaxf(fmaxf(s[0], s[1]), fmaxf(s[4], s[5]));
            float m1 = fmaxf(fmaxf(s[2], s[3]), fmaxf(s[6], s[7]));
            m0 = fmaxf(m0, __shfl_xor_sync(0xffffffffu, m0, 1));
            m0 = fmaxf(m0, __shfl_xor_sync(0xffffffffu, m0, 2));
            m1 = fmaxf(m1, __shfl_xor_sync(0xffffffffu, m1, 1));
            m1 = fmaxf(m1, __shfl_xor_sync(0xffffffffu, m1, 2));
            s[0] = __expf(s[0] - m0); s[1] = __expf(s[1] - m0);
            s[4] = __expf(s[4] - m0); s[5] = __expf(s[5] - m0);
            s[2] = __expf(s[2] - m1); s[3] = __expf(s[3] - m1);
            s[6] = __expf(s[6] - m1); s[7] = __expf(s[7] - m1);
            float t0 = s[0] + s[1] + s[4] + s[5];
            float t1 = s[2] + s[3] + s[6] + s[7];
            t0 += __shfl_xor_sync(0xffffffffu, t0, 1);
            t0 += __shfl_xor_sync(0xffffffffu, t0, 2);
            t1 += __shfl_xor_sync(0xffffffffu, t1, 1);
            t1 += __shfl_xor_sync(0xffffffffu, t1, 2);
            float i0 = 1.f / t0, i1 = 1.f / t1;
            s[0] *= i0; s[1] *= i0; s[4] *= i0; s[5] *= i0;
            s[2] *= i1; s[3] *= i1; s[6] *= i1; s[7] *= i1;

            uint32_t *ph = side ? pahB : pahA;
            ph[0] = packh(s[0], s[1]);
            ph[1] = packh(s[2], s[3]);
            ph[2] = packh(s[4], s[5]);
            ph[3] = packh(s[6], s[7]);
        }

        // ---- ctx = P@V (per batch; B from vT smem) ----
#pragma unroll
        for (int i2 = 0; i2 < 16; i2++) { CA[i2] = 0.f; CB[i2] = 0.f; }
#pragma unroll
        for (int j = 0; j < 4; j++) {
            const unsigned short *pA = vtA + (8*j + g)*VS + 2*t;
            uint32_t a0 = *(const uint32_t*)pA, a1 = *(const uint32_t*)(pA + 8);
            mma16816(CA[j*4+0],CA[j*4+1],CA[j*4+2],CA[j*4+3],
                     pahA[0],pahA[1],pahA[2],pahA[3], a0,a1);
            const unsigned short *pB = vtB + (8*j + g)*VS + 2*t;
            uint32_t c0 = *(const uint32_t*)pB, c1 = *(const uint32_t*)(pB + 8);
            mma16816(CB[j*4+0],CB[j*4+1],CB[j*4+2],CB[j*4+3],
                     pahB[0],pahB[1],pahB[2],pahB[3], c0,c1);
        }

        // ---- y = (init: x + bo) + ctx@Wo ----
        uint32_t cahA[8], cahB[8];
        c2a_hi<2>(CA, cahA);
        c2a_hi<2>(CB, cahB);
        float yvA[16], yvB[16];
#pragma unroll
        for (int nc = 0; nc < 4; nc++) {
            float2 bb = *(const float2*)(smf + 96 + 8*nc + 2*t);
            yvA[nc*4+0] = xcA[nc*4+0] + bb.x;
            yvA[nc*4+1] = xcA[nc*4+1] + bb.y;
            yvA[nc*4+2] = xcA[nc*4+2] + bb.x;
            yvA[nc*4+3] = xcA[nc*4+3] + bb.y;
            yvB[nc*4+0] = xcB[nc*4+0] + bb.x;
            yvB[nc*4+1] = xcB[nc*4+1] + bb.y;
            yvB[nc*4+2] = xcB[nc*4+2] + bb.x;
            yvB[nc*4+3] = xcB[nc*4+3] + bb.y;
        }
        gemm1w<2,4,40>(yvA, yvB, cahA, cahB, sm16 + WOH, g, t);

        // ---- FFN: z init = y + b2; accumulate h@W2 over two halves ----
        uint32_t yahA[8], yahB[8];
        c2a_hi<2>(yvA, yahA);
        c2a_hi<2>(yvB, yahB);
        float zvA[16], zvB[16];
#pragma unroll
        for (int nc = 0; nc < 4; nc++) {
            float2 bb = *(const float2*)(smf + 192 + 8*nc + 2*t);
            zvA[nc*4+0] = yvA[nc*4+0] + bb.x;
            zvA[nc*4+1] = yvA[nc*4+1] + bb.y;
            zvA[nc*4+2] = yvA[nc*4+2] + bb.x;
            zvA[nc*4+3] = yvA[nc*4+3] + bb.y;
            zvB[nc*4+0] = yvB[nc*4+0] + bb.x;
            zvB[nc*4+1] = yvB[nc*4+1] + bb.y;
            zvB[nc*4+2] = yvB[nc*4+2] + bb.x;
            zvB[nc*4+3] = yvB[nc*4+3] + bb.y;
        }
#pragma unroll
        for (int fh = 0; fh < 2; fh++) {
            float hbA[16], hbB[16];
            initCb(hbA, smf + 128 + fh*32, t);
            initCb(hbB, smf + 128 + fh*32, t);
            gemm1w<2,4,40>(hbA, hbB, yahA, yahB, sm16 + W1H + fh*32*40, g, t);
#pragma unroll
            for (int i2 = 0; i2 < 16; i2++) {
                hbA[i2] = fmaxf(hbA[i2], 0.f);
                hbB[i2] = fmaxf(hbB[i2], 0.f);
            }
            uint32_t hahA[8], hahB[8];
            c2a_hi<2>(hbA, hahA);
            c2a_hi<2>(hbB, hahB);
            gemm1w<2,4,72>(zvA, zvB, hahA, hahB, sm16 + W2H + fh*32, g, t);
        }

        // ---- store z (complete in zv) ----
        float2 *opA = (float2*)(out + b0 * 512);
#pragma unroll
        for (int nc = 0; nc < 4; nc++) {
            opA[g*16 + nc*4 + t]     = make_float2(zvA[nc*4+0], zvA[nc*4+1]);
            opA[(g+8)*16 + nc*4 + t] = make_float2(zvA[nc*4+2], zvA[nc*4+3]);
        }
        if (v1) {
            float2 *opB = (float2*)(out + b1s * 512);
#pragma unroll
            for (int nc = 0; nc < 4; nc++) {
                opB[g*16 + nc*4 + t]     = make_float2(zvB[nc*4+0], zvB[nc*4+1]);
                opB[(g+8)*16 + nc*4 + t] = make_float2(zvB[nc*4+2], zvB[nc*4+3]);
            }
        }
        __syncwarp();   // vT staging reuse barrier for next pair
    }
}

extern "C" void kernel_launch(void* const* d_in, const int* in_sizes, int n_in,
                              void* d_out, int out_size)
{
    const float* x  = (const float*)d_in[0];
    const float* Wq = (const float*)d_in[1];
    const float* bq = (const float*)d_in[2];
    const float* Wk = (const float*)d_in[3];
    const float* bk = (const float*)d_in[4];
    const float* Wv = (const float*)d_in[5];
    const float* bv = (const float*)d_in[6];
    const float* Wo = (const float*)d_in[7];
    const float* bo = (const float*)d_in[8];
    const float* W1 = (const float*)d_in[9];
    const float* b1 = (const float*)d_in[10];
    const float* W2 = (const float*)d_in[11];
    const float* b2 = (const float*)d_in[12];
    float* out = (float*)d_out;

    const int B = in_sizes[0] / 512;                                    // 65536
    const int blocks = (B + BATCHES_PER_BLOCK - 1) / BATCHES_PER_BLOCK; // 2048

    cudaFuncSetAttribute(tinyformer_tc_kernel,
                         cudaFuncAttributeMaxDynamicSharedMemorySize, SMEM_BYTES);
    tinyformer_tc_kernel<<<blocks, THREADS, SMEM_BYTES>>>(x, Wq, bq, Wk, bk, Wv, bv,
                                                          Wo, bo, W1, b1, W2, b2, out, B);
}